// round 15
// baseline (speedup 1.0000x reference)
#include <cuda_runtime.h>
#include <cuda_fp16.h>
#include <math.h>
#include <stdint.h>

#define B_ 8192
#define D_ 128
#define NT_ 64                            // number of 128-row tiles
#define NPAIRS ((NT_ * (NT_ + 1)) / 2)    // 2080 upper-triangular tile pairs
#define GRID_ 296                         // 2 persistent CTAs per SM

// Smem tiles: 128 rows x 128 halves (256B) padded to 272B (stride ≡ 16 mod 128
// => ldmatrix 8-row groups hit banks conflict-free). Single tile buffer,
// prefetched in place; q codes double-buffered (epilogue overlap).
#define ROWB 272
#define TILE_BYTES (128 * ROWB)           // 34816
#define OFF_A 0
#define OFF_B TILE_BYTES
#define OFF_Q  (2 * TILE_BYTES)           // q[2][256] floats
#define SMEM_BYTES (OFF_Q + 2 * 256 * 4)  // 71680 (x2 CTAs = 143360 <= 228KB)

__device__ __align__(16) __half g_eH[B_ * D_];  // scaled by sqrt(log2e/T), fp16
__device__ float g_q[B_];    // class code: sign(conf) * (label==1 ? 1 : 2)
__device__ float g_pos[B_];
__device__ float g_neg[B_];

// ---------------------------------------------------------------------------
__device__ __forceinline__ uint32_t smem_u32(const void* p) {
    uint32_t a;
    asm("{ .reg .u64 t; cvta.to.shared.u64 t, %1; cvt.u32.u64 %0, t; }" : "=r"(a) : "l"(p));
    return a;
}
__device__ __forceinline__ __half2 h2ex2(__half2 x) {
    __half2 y;
    asm("ex2.approx.f16x2 %0, %1;"
        : "=r"(*reinterpret_cast<uint32_t*>(&y))
        : "r"(*reinterpret_cast<uint32_t*>(&x)));
    return y;
}
__device__ __forceinline__ void cpasync16(uint32_t saddr, const void* g) {
    asm volatile("cp.async.cg.shared.global [%0], [%1], 16;" :: "r"(saddr), "l"(g));
}
#define CP_COMMIT() asm volatile("cp.async.commit_group;" ::: "memory")
#define CP_WAIT0()  asm volatile("cp.async.wait_group 0;" ::: "memory")

__device__ __forceinline__ void ldm_x4(uint32_t* r, uint32_t addr) {
    asm volatile("ldmatrix.sync.aligned.m8n8.x4.shared.b16 {%0,%1,%2,%3}, [%4];"
                 : "=r"(r[0]), "=r"(r[1]), "=r"(r[2]), "=r"(r[3]) : "r"(addr));
}
__device__ __forceinline__ void mma_f16acc(uint32_t* d, const uint32_t* a, const uint32_t* b) {
    asm volatile(
        "mma.sync.aligned.m16n8k16.row.col.f16.f16.f16.f16 "
        "{%0,%1}, {%2,%3,%4,%5}, {%6,%7}, {%0,%1};"
        : "+r"(d[0]), "+r"(d[1])
        : "r"(a[0]), "r"(a[1]), "r"(a[2]), "r"(a[3]), "r"(b[0]), "r"(b[1]));
}

// Triangular decode: idx -> (ti, tj), ti <= tj. Float sqrt + exact fixups.
#define FTRI(i) ((i) * (2 * NT_ - (i) + 1) / 2)
__device__ __forceinline__ void tri_decode(int idx, int& ti, int& tj) {
    float f = 2.f * NT_ + 1.f;
    int t = (int)((f - sqrtf(fmaxf(f * f - 8.f * (float)idx, 0.f))) * 0.5f);
    if (t < 0) t = 0;
    if (t > NT_ - 1) t = NT_ - 1;
    while (t > 0 && FTRI(t) > idx) t--;
    while (FTRI(t + 1) <= idx) t++;
    ti = t;
    tj = t + (idx - FTRI(t));
}

// ---------------------------------------------------------------------------
// Kernel 1: normalize rows, fold in sqrt(log2e/T), fp16-round, zero sums.
// 256 threads; each warp handles 4 rows; each lane 16 floats (MLP 4).
// ---------------------------------------------------------------------------
__global__ void prep_kernel(const float* __restrict__ emb,
                            const int*   __restrict__ labels,
                            const float* __restrict__ conf) {
    int wid  = threadIdx.x >> 5;
    int lane = threadIdx.x & 31;
    int row  = blockIdx.x * 32 + wid * 4 + (lane >> 3);
    int seg  = lane & 7;                  // 16-float segment within the row
    const float4* src = (const float4*)(emb + (size_t)row * D_) + seg * 4;
    float4 v0 = src[0], v1 = src[1], v2 = src[2], v3 = src[3];
    float ss = v0.x*v0.x + v0.y*v0.y + v0.z*v0.z + v0.w*v0.w
             + v1.x*v1.x + v1.y*v1.y + v1.z*v1.z + v1.w*v1.w
             + v2.x*v2.x + v2.y*v2.y + v2.z*v2.z + v2.w*v2.w
             + v3.x*v3.x + v3.y*v3.y + v3.z*v3.z + v3.w*v3.w;
    ss += __shfl_xor_sync(0xffffffffu, ss, 1);
    ss += __shfl_xor_sync(0xffffffffu, ss, 2);
    ss += __shfl_xor_sync(0xffffffffu, ss, 4);
    const float SCALE = 3.7982826f;   // sqrt(log2(e) / 0.1)
    float s = SCALE / fmaxf(sqrtf(ss), 1e-12f);
    __half2 h0 = __floats2half2_rn(v0.x * s, v0.y * s);
    __half2 h1 = __floats2half2_rn(v0.z * s, v0.w * s);
    __half2 h2 = __floats2half2_rn(v1.x * s, v1.y * s);
    __half2 h3 = __floats2half2_rn(v1.z * s, v1.w * s);
    __half2 h4 = __floats2half2_rn(v2.x * s, v2.y * s);
    __half2 h5 = __floats2half2_rn(v2.z * s, v2.w * s);
    __half2 h6 = __floats2half2_rn(v3.x * s, v3.y * s);
    __half2 h7 = __floats2half2_rn(v3.z * s, v3.w * s);
    uint4 o0 = { *(uint32_t*)&h0, *(uint32_t*)&h1, *(uint32_t*)&h2, *(uint32_t*)&h3 };
    uint4 o1 = { *(uint32_t*)&h4, *(uint32_t*)&h5, *(uint32_t*)&h6, *(uint32_t*)&h7 };
    uint4* dst = (uint4*)(g_eH + (size_t)row * D_) + seg * 2;
    dst[0] = o0;
    dst[1] = o1;
    if (seg == 0) {
        float c = conf[row];
        float sg = (c > 0.f) ? 1.f : ((c < 0.f) ? -1.f : 0.f);
        g_q[row] = sg * ((labels[row] == 1) ? 1.f : 2.f);
        g_pos[row] = 0.f;
        g_neg[row] = 0.f;
    }
}

// ---------------------------------------------------------------------------
// Kernel 2: persistent fp16 mma.sync tiles (2 CTAs/SM), in-place tile prefetch
// overlapped with the epilogue, q codes double-buffered. Epilogue accumulates
// tot=e*(p>0) and neg=e*(p==2); pos=tot-neg formed once at reduction.
// 512 threads = 16 warps (4x4); each warp owns a 32x32 micro-tile.
// ---------------------------------------------------------------------------
__global__ void __launch_bounds__(512, 2) sim_kernel() {
    extern __shared__ char smem[];
    const uint32_t sb = smem_u32(smem);

    const int tid  = threadIdx.x;
    const int wid  = tid >> 5;
    const int lane = tid & 31;
    const int grp  = lane >> 2;     // 0..7
    const int qid  = lane & 3;      // 0..3
    const int wr   = wid >> 2;      // warp row
    const int wc   = wid & 3;       // warp col

    float* qsm = (float*)(smem + OFF_Q);   // [2][256]

    // ldmatrix lane-address components (constant across tiles).
    const uint32_t aAddr0 = sb + OFF_A + (uint32_t)((wr * 32 + (lane & 15)) * ROWB)
                          + (uint32_t)((lane >> 4) * 16);
    const uint32_t bAddr0 = sb + OFF_B + (uint32_t)((wc * 32 + ((lane >> 4) & 1) * 8 + (lane & 7)) * ROWB)
                          + (uint32_t)(((lane >> 3) & 1) * 16);

    const __half2 ZERO2 = __float2half2_rn(0.f);
    const __half2 TWO2  = __float2half2_rn(2.f);

    // Fill: A/B tile pair into the single tile buffer + q codes into buf qb.
    auto issue_fill = [&](int ti, int tj, int qb) {
        const char* srcA = (const char*)(g_eH + (size_t)(ti * 128) * D_);
        const char* srcB = (const char*)(g_eH + (size_t)(tj * 128) * D_);
        #pragma unroll
        for (int it = 0; it < 4; it++) {
            int tt = tid + it * 512;
            int row = tt >> 4, kg = tt & 15;
            uint32_t doff = (uint32_t)(row * ROWB + kg * 16);
            size_t soff = (size_t)row * 256 + (size_t)kg * 16;
            cpasync16(sb + OFF_A + doff, srcA + soff);
            cpasync16(sb + OFF_B + doff, srcB + soff);
        }
        CP_COMMIT();
        if (tid < 128)       qsm[qb * 256 + tid] = g_q[ti * 128 + tid];
        else if (tid < 256)  qsm[qb * 256 + tid] = g_q[tj * 128 + (tid - 128)];
    };

    // Prologue: prefetch first tile into buffer, q into buf 0.
    {
        int ti0, tj0;
        tri_decode(blockIdx.x, ti0, tj0);
        issue_fill(ti0, tj0, 0);
    }

    int qb = 0;
    for (int t = blockIdx.x; t < NPAIRS; t += GRID_) {
        int ti, tj;
        tri_decode(t, ti, tj);
        const int i0 = ti * 128;
        const int j0 = tj * 128;
        const bool offdiag = (ti != tj);

        CP_WAIT0();
        __syncthreads();   // tile t + q codes visible; prev epilogue done

        uint32_t acc[2][4][2] = {};   // [mt][nt][q] half2 accumulators

        #pragma unroll
        for (int ks = 0; ks < 8; ks++) {
            const uint32_t ko = (uint32_t)(ks * 32);   // 16 halves = 32B per kstep
            uint32_t af[2][4], bf[2][4];
            ldm_x4(af[0], aAddr0 + ko);
            ldm_x4(af[1], aAddr0 + (uint32_t)(16 * ROWB) + ko);
            ldm_x4(bf[0], bAddr0 + ko);
            ldm_x4(bf[1], bAddr0 + (uint32_t)(16 * ROWB) + ko);
            #pragma unroll
            for (int mt = 0; mt < 2; mt++)
                #pragma unroll
                for (int nt = 0; nt < 4; nt++)
                    mma_f16acc(acc[mt][nt], af[mt], &bf[nt >> 1][(nt & 1) * 2]);
        }

        __syncthreads();   // all warps done reading tile smem buffers

        // Prefetch next tile in place; lands while the epilogue runs.
        int tn = t + GRID_;
        if (tn < NPAIRS) {
            int tin, tjn;
            tri_decode(tn, tin, tjn);
            issue_fill(tin, tjn, qb ^ 1);
        }

        // ---------------- Epilogue (half2): tot/neg accumulation ----------------
        const float* qi_sh = qsm + qb * 256;       // current tile's q codes
        const float* qj_sh = qi_sh + 128;
        __half2 fih[4], fjh[4];
        #pragma unroll
        for (int mt = 0; mt < 2; mt++) {
            fih[mt * 2 + 0] = __float2half2_rn(qi_sh[wr * 32 + mt * 16 + grp]);
            fih[mt * 2 + 1] = __float2half2_rn(qi_sh[wr * 32 + mt * 16 + grp + 8]);
        }
        #pragma unroll
        for (int nt = 0; nt < 4; nt++) {
            int c0 = wc * 32 + nt * 8 + 2 * qid;
            fjh[nt] = __floats2half2_rn(qj_sh[c0], qj_sh[c0 + 1]);
        }

        __half2 ts2[4], ns2[4], ct2[4], cn2[4];   // tot / neg (rows, cols)
        #pragma unroll
        for (int k = 0; k < 4; k++) {
            ts2[k] = ZERO2; ns2[k] = ZERO2;
            ct2[k] = ZERO2; cn2[k] = ZERO2;
        }

        if (offdiag) {
            #pragma unroll
            for (int mt = 0; mt < 2; mt++)
                #pragma unroll
                for (int nt = 0; nt < 4; nt++)
                    #pragma unroll
                    for (int q = 0; q < 2; q++) {
                        __half2 e = h2ex2(*reinterpret_cast<__half2*>(&acc[mt][nt][q]));
                        __half2 p = __hmul2(fih[mt * 2 + q], fjh[nt]);
                        __half2 m = __hgt2(p, ZERO2);      // tot mask: pos|neg
                        __half2 n = __heq2(p, TWO2);       // neg mask
                        ts2[mt * 2 + q] = __hfma2(e, m, ts2[mt * 2 + q]);
                        ns2[mt * 2 + q] = __hfma2(e, n, ns2[mt * 2 + q]);
                        ct2[nt] = __hfma2(e, m, ct2[nt]);
                        cn2[nt] = __hfma2(e, n, cn2[nt]);
                    }
        } else {
            // Diagonal tile: kill i==j in the tot mask BEFORE accumulation
            // (self term 2^14.4 would swamp fp16 partials; self is pos-class,
            // so excluding it from tot keeps tot = pos+neg). No col sums.
            #pragma unroll
            for (int mt = 0; mt < 2; mt++)
                #pragma unroll
                for (int nt = 0; nt < 4; nt++)
                    #pragma unroll
                    for (int q = 0; q < 2; q++) {
                        int row = wr * 32 + mt * 16 + grp + q * 8;
                        int c0  = wc * 32 + nt * 8 + 2 * qid;
                        __half2 e = h2ex2(*reinterpret_cast<__half2*>(&acc[mt][nt][q]));
                        __half2 p = __hmul2(fih[mt * 2 + q], fjh[nt]);
                        __half2 dk = __floats2half2_rn(row == c0 ? 0.f : 1.f,
                                                       row == c0 + 1 ? 0.f : 1.f);
                        __half2 m = __hmul2(__hgt2(p, ZERO2), dk);
                        __half2 n = __heq2(p, TWO2);
                        ts2[mt * 2 + q] = __hfma2(e, m, ts2[mt * 2 + q]);
                        ns2[mt * 2 + q] = __hfma2(e, n, ns2[mt * 2 + q]);
                    }
        }

        // Row reduce: packed half2 shfl over qid (xor 1,2); unpack at the end.
        #pragma unroll
        for (int r = 0; r < 4; r++) {
            #pragma unroll
            for (int o = 1; o <= 2; o <<= 1) {
                uint32_t ut = __shfl_xor_sync(0xffffffffu, *reinterpret_cast<uint32_t*>(&ts2[r]), o);
                uint32_t un = __shfl_xor_sync(0xffffffffu, *reinterpret_cast<uint32_t*>(&ns2[r]), o);
                ts2[r] = __hadd2(ts2[r], *reinterpret_cast<__half2*>(&ut));
                ns2[r] = __hadd2(ns2[r], *reinterpret_cast<__half2*>(&un));
            }
        }
        if (qid == 0) {
            #pragma unroll
            for (int r = 0; r < 4; r++) {
                int gi = i0 + wr * 32 + (r >> 1) * 16 + grp + (r & 1) * 8;
                float2 tv = __half22float2(ts2[r]);
                float2 nv = __half22float2(ns2[r]);
                float tot = tv.x + tv.y;
                float neg = nv.x + nv.y;
                atomicAdd(&g_pos[gi], tot - neg);
                atomicAdd(&g_neg[gi], neg);
            }
        }

        // Col reduce (off-diag only): packed half2 shfl over grp (xor 4,8,16).
        if (offdiag) {
            #pragma unroll
            for (int c = 0; c < 4; c++) {
                #pragma unroll
                for (int o = 4; o <= 16; o <<= 1) {
                    uint32_t ut = __shfl_xor_sync(0xffffffffu, *reinterpret_cast<uint32_t*>(&ct2[c]), o);
                    uint32_t un = __shfl_xor_sync(0xffffffffu, *reinterpret_cast<uint32_t*>(&cn2[c]), o);
                    ct2[c] = __hadd2(ct2[c], *reinterpret_cast<__half2*>(&ut));
                    cn2[c] = __hadd2(cn2[c], *reinterpret_cast<__half2*>(&un));
                }
            }
            if (grp == 0) {
                #pragma unroll
                for (int c = 0; c < 4; c++) {
                    int gj = j0 + wc * 32 + c * 8 + 2 * qid;
                    float2 tv = __half22float2(ct2[c]);
                    float2 nv = __half22float2(cn2[c]);
                    atomicAdd(&g_pos[gj],     tv.x - nv.x);
                    atomicAdd(&g_pos[gj + 1], tv.y - nv.y);
                    atomicAdd(&g_neg[gj],     nv.x);
                    atomicAdd(&g_neg[gj + 1], nv.y);
                }
            }
        }

        qb ^= 1;
    }
}

// ---------------------------------------------------------------------------
// Kernel 3: final loss reduction over rows (256 threads, shfl reduce).
// ---------------------------------------------------------------------------
__global__ void loss_kernel(float* __restrict__ out, int B) {
    __shared__ float s1[8], s2[8];
    int tid  = threadIdx.x;
    int lane = tid & 31;
    int wid  = tid >> 5;
    float tot = 0.f, cnt = 0.f;
    for (int i = tid; i < B; i += 256) {
        float p = g_pos[i], n = g_neg[i];
        if (p > 0.f && n > 0.f) {
            tot += -__logf(p / (p + n + 1e-8f));
            cnt += 1.f;
        }
    }
    #pragma unroll
    for (int o = 16; o; o >>= 1) {
        tot += __shfl_xor_sync(0xffffffffu, tot, o);
        cnt += __shfl_xor_sync(0xffffffffu, cnt, o);
    }
    if (lane == 0) { s1[wid] = tot; s2[wid] = cnt; }
    __syncthreads();
    if (wid == 0 && lane < 8) {
        tot = s1[lane]; cnt = s2[lane];
        #pragma unroll
        for (int o = 4; o; o >>= 1) {
            tot += __shfl_xor_sync(0xffu, tot, o);
            cnt += __shfl_xor_sync(0xffu, cnt, o);
        }
        if (lane == 0) out[0] = (cnt > 0.f) ? (tot / cnt) : 0.f;
    }
}

extern "C" void kernel_launch(void* const* d_in, const int* in_sizes, int n_in,
                              void* d_out, int out_size) {
    const float* emb    = (const float*)d_in[0];
    const int*   labels = (const int*)  d_in[1];
    const float* conf   = (const float*)d_in[2];
    int B = in_sizes[1];   // 8192
    (void)n_in; (void)out_size;

    cudaFuncSetAttribute(sim_kernel, cudaFuncAttributeMaxDynamicSharedMemorySize, SMEM_BYTES);

    prep_kernel<<<B / 32, 256>>>(emb, labels, conf);
    sim_kernel<<<GRID_, 512, SMEM_BYTES>>>();
    loss_kernel<<<1, 256>>>((float*)d_out, B);
}

// round 16
// speedup vs baseline: 1.0068x; 1.0068x over previous
#include <cuda_runtime.h>
#include <cuda_fp16.h>
#include <math.h>
#include <stdint.h>

#define B_ 8192
#define D_ 128
#define NT_ 64                            // number of 128-row tiles
#define NPAIRS ((NT_ * (NT_ + 1)) / 2)    // 2080 upper-triangular tile pairs
#define GRID_ 296                         // 2 persistent CTAs per SM

// Smem: A single-buffered (in-place prefetch, lands under epilogue),
// B double-buffered (prefetch issued BEFORE the mainloop -> whole mainloop
// to land). Rows padded to 272B (stride ≡ 16 mod 128 => ldmatrix conflict-free).
#define ROWB 272
#define TILE_BYTES (128 * ROWB)           // 34816
#define OFF_A  0
#define OFF_B0 TILE_BYTES
#define OFF_B1 (2 * TILE_BYTES)
#define OFF_Q  (3 * TILE_BYTES)           // q[2][256] floats
#define SMEM_BYTES (OFF_Q + 2 * 256 * 4)  // 106496 (x2 CTAs = 212992 <= 227KB)

__device__ __align__(16) __half g_eH[B_ * D_];  // scaled by sqrt(log2e/T), fp16
__device__ float g_q[B_];    // class code: sign(conf) * (label==1 ? 1 : 2)
__device__ float g_pos[B_];
__device__ float g_neg[B_];

// ---------------------------------------------------------------------------
__device__ __forceinline__ uint32_t smem_u32(const void* p) {
    uint32_t a;
    asm("{ .reg .u64 t; cvta.to.shared.u64 t, %1; cvt.u32.u64 %0, t; }" : "=r"(a) : "l"(p));
    return a;
}
__device__ __forceinline__ __half2 h2ex2(__half2 x) {
    __half2 y;
    asm("ex2.approx.f16x2 %0, %1;"
        : "=r"(*reinterpret_cast<uint32_t*>(&y))
        : "r"(*reinterpret_cast<uint32_t*>(&x)));
    return y;
}
__device__ __forceinline__ void cpasync16(uint32_t saddr, const void* g) {
    asm volatile("cp.async.cg.shared.global [%0], [%1], 16;" :: "r"(saddr), "l"(g));
}
#define CP_COMMIT() asm volatile("cp.async.commit_group;" ::: "memory")
#define CP_WAIT0()  asm volatile("cp.async.wait_group 0;" ::: "memory")

__device__ __forceinline__ void ldm_x4(uint32_t* r, uint32_t addr) {
    asm volatile("ldmatrix.sync.aligned.m8n8.x4.shared.b16 {%0,%1,%2,%3}, [%4];"
                 : "=r"(r[0]), "=r"(r[1]), "=r"(r[2]), "=r"(r[3]) : "r"(addr));
}
__device__ __forceinline__ void mma_f16acc(uint32_t* d, const uint32_t* a, const uint32_t* b) {
    asm volatile(
        "mma.sync.aligned.m16n8k16.row.col.f16.f16.f16.f16 "
        "{%0,%1}, {%2,%3,%4,%5}, {%6,%7}, {%0,%1};"
        : "+r"(d[0]), "+r"(d[1])
        : "r"(a[0]), "r"(a[1]), "r"(a[2]), "r"(a[3]), "r"(b[0]), "r"(b[1]));
}

// Triangular decode: idx -> (ti, tj), ti <= tj. Float sqrt + exact fixups.
#define FTRI(i) ((i) * (2 * NT_ - (i) + 1) / 2)
__device__ __forceinline__ void tri_decode(int idx, int& ti, int& tj) {
    float f = 2.f * NT_ + 1.f;
    int t = (int)((f - sqrtf(fmaxf(f * f - 8.f * (float)idx, 0.f))) * 0.5f);
    if (t < 0) t = 0;
    if (t > NT_ - 1) t = NT_ - 1;
    while (t > 0 && FTRI(t) > idx) t--;
    while (FTRI(t + 1) <= idx) t++;
    ti = t;
    tj = t + (idx - FTRI(t));
}

// ---------------------------------------------------------------------------
// Kernel 1: normalize rows, fold in sqrt(log2e/T), fp16-round, zero sums.
// ---------------------------------------------------------------------------
__global__ void prep_kernel(const float* __restrict__ emb,
                            const int*   __restrict__ labels,
                            const float* __restrict__ conf) {
    int wid  = threadIdx.x >> 5;
    int lane = threadIdx.x & 31;
    int row  = blockIdx.x * 32 + wid * 4 + (lane >> 3);
    int seg  = lane & 7;                  // 16-float segment within the row
    const float4* src = (const float4*)(emb + (size_t)row * D_) + seg * 4;
    float4 v0 = src[0], v1 = src[1], v2 = src[2], v3 = src[3];
    float ss = v0.x*v0.x + v0.y*v0.y + v0.z*v0.z + v0.w*v0.w
             + v1.x*v1.x + v1.y*v1.y + v1.z*v1.z + v1.w*v1.w
             + v2.x*v2.x + v2.y*v2.y + v2.z*v2.z + v2.w*v2.w
             + v3.x*v3.x + v3.y*v3.y + v3.z*v3.z + v3.w*v3.w;
    ss += __shfl_xor_sync(0xffffffffu, ss, 1);
    ss += __shfl_xor_sync(0xffffffffu, ss, 2);
    ss += __shfl_xor_sync(0xffffffffu, ss, 4);
    const float SCALE = 3.7982826f;   // sqrt(log2(e) / 0.1)
    float s = SCALE / fmaxf(sqrtf(ss), 1e-12f);
    __half2 h0 = __floats2half2_rn(v0.x * s, v0.y * s);
    __half2 h1 = __floats2half2_rn(v0.z * s, v0.w * s);
    __half2 h2 = __floats2half2_rn(v1.x * s, v1.y * s);
    __half2 h3 = __floats2half2_rn(v1.z * s, v1.w * s);
    __half2 h4 = __floats2half2_rn(v2.x * s, v2.y * s);
    __half2 h5 = __floats2half2_rn(v2.z * s, v2.w * s);
    __half2 h6 = __floats2half2_rn(v3.x * s, v3.y * s);
    __half2 h7 = __floats2half2_rn(v3.z * s, v3.w * s);
    uint4 o0 = { *(uint32_t*)&h0, *(uint32_t*)&h1, *(uint32_t*)&h2, *(uint32_t*)&h3 };
    uint4 o1 = { *(uint32_t*)&h4, *(uint32_t*)&h5, *(uint32_t*)&h6, *(uint32_t*)&h7 };
    uint4* dst = (uint4*)(g_eH + (size_t)row * D_) + seg * 2;
    dst[0] = o0;
    dst[1] = o1;
    if (seg == 0) {
        float c = conf[row];
        float sg = (c > 0.f) ? 1.f : ((c < 0.f) ? -1.f : 0.f);
        g_q[row] = sg * ((labels[row] == 1) ? 1.f : 2.f);
        g_pos[row] = 0.f;
        g_neg[row] = 0.f;
    }
}

// ---------------------------------------------------------------------------
// Kernel 2: persistent fp16 mma.sync tiles (2 CTAs/SM). B double-buffered
// (prefetched before the mainloop), A prefetched in place under the epilogue,
// q codes double-buffered. Epilogue: tot/neg half2 accumulation.
// 512 threads = 16 warps (4x4); each warp owns a 32x32 micro-tile.
// ---------------------------------------------------------------------------
__global__ void __launch_bounds__(512, 2) sim_kernel() {
    extern __shared__ char smem[];
    const uint32_t sb = smem_u32(smem);

    const int tid  = threadIdx.x;
    const int wid  = tid >> 5;
    const int lane = tid & 31;
    const int grp  = lane >> 2;     // 0..7
    const int qid  = lane & 3;      // 0..3
    const int wr   = wid >> 2;      // warp row
    const int wc   = wid & 3;       // warp col

    float* qsm = (float*)(smem + OFF_Q);   // [2][256]

    // ldmatrix lane-address components (constant across tiles).
    const uint32_t aAddr0 = sb + OFF_A + (uint32_t)((wr * 32 + (lane & 15)) * ROWB)
                          + (uint32_t)((lane >> 4) * 16);
    const uint32_t bRel   = (uint32_t)((wc * 32 + ((lane >> 4) & 1) * 8 + (lane & 7)) * ROWB)
                          + (uint32_t)(((lane >> 3) & 1) * 16);

    const __half2 ZERO2 = __float2half2_rn(0.f);
    const __half2 TWO2  = __float2half2_rn(2.f);

    // B fill into buffer bbuf (8 x 16B chunks per thread... 4 per thread here).
    auto fill_B = [&](int tj, int bbuf) {
        const char* srcB = (const char*)(g_eH + (size_t)(tj * 128) * D_);
        uint32_t offB = bbuf ? OFF_B1 : OFF_B0;
        #pragma unroll
        for (int it = 0; it < 4; it++) {
            int tt = tid + it * 512;
            int row = tt >> 4, kg = tt & 15;
            uint32_t doff = (uint32_t)(row * ROWB + kg * 16);
            size_t soff = (size_t)row * 256 + (size_t)kg * 16;
            cpasync16(sb + offB + doff, srcB + soff);
        }
        CP_COMMIT();
    };
    // A fill (in place) + q codes for tile (ti, tj) into q buffer qbuf.
    auto fill_A_q = [&](int ti, int tj, int qbuf) {
        const char* srcA = (const char*)(g_eH + (size_t)(ti * 128) * D_);
        #pragma unroll
        for (int it = 0; it < 4; it++) {
            int tt = tid + it * 512;
            int row = tt >> 4, kg = tt & 15;
            uint32_t doff = (uint32_t)(row * ROWB + kg * 16);
            size_t soff = (size_t)row * 256 + (size_t)kg * 16;
            cpasync16(sb + OFF_A + doff, srcA + soff);
        }
        CP_COMMIT();
        if (tid < 128)       qsm[qbuf * 256 + tid] = g_q[ti * 128 + tid];
        else if (tid < 256)  qsm[qbuf * 256 + tid] = g_q[tj * 128 + (tid - 128)];
    };

    // Prologue: fill tile 0 (A + B into buf 0, q into buf 0).
    {
        int ti0, tj0;
        tri_decode(blockIdx.x, ti0, tj0);
        fill_B(tj0, 0);
        fill_A_q(ti0, tj0, 0);
    }

    int qb = 0, bb = 0;
    for (int t = blockIdx.x; t < NPAIRS; t += GRID_) {
        int ti, tj;
        tri_decode(t, ti, tj);
        const int i0 = ti * 128;
        const int j0 = tj * 128;
        const bool offdiag = (ti != tj);

        CP_WAIT0();
        __syncthreads();   // tile t (A + B[bb]) + q codes visible

        // Prefetch NEXT tile's B into the other buffer: gets the whole
        // mainloop + epilogue to land.
        int tn = t + GRID_;
        if (tn < NPAIRS) {
            int tin, tjn;
            tri_decode(tn, tin, tjn);
            fill_B(tjn, bb ^ 1);
        }

        const uint32_t bAddr0 = sb + (bb ? OFF_B1 : OFF_B0) + bRel;

        uint32_t acc[2][4][2] = {};   // [mt][nt][q] half2 accumulators

        #pragma unroll
        for (int ks = 0; ks < 8; ks++) {
            const uint32_t ko = (uint32_t)(ks * 32);   // 16 halves = 32B per kstep
            uint32_t af[2][4], bf[2][4];
            ldm_x4(af[0], aAddr0 + ko);
            ldm_x4(af[1], aAddr0 + (uint32_t)(16 * ROWB) + ko);
            ldm_x4(bf[0], bAddr0 + ko);
            ldm_x4(bf[1], bAddr0 + (uint32_t)(16 * ROWB) + ko);
            #pragma unroll
            for (int mt = 0; mt < 2; mt++)
                #pragma unroll
                for (int nt = 0; nt < 4; nt++)
                    mma_f16acc(acc[mt][nt], af[mt], &bf[nt >> 1][(nt & 1) * 2]);
        }

        __syncthreads();   // all warps done reading A tile + qsm[qb^1] free

        // Prefetch next tile's A in place + q codes; lands under the epilogue.
        if (tn < NPAIRS) {
            int tin, tjn;
            tri_decode(tn, tin, tjn);
            fill_A_q(tin, tjn, qb ^ 1);
        }

        // ---------------- Epilogue (half2): tot/neg accumulation ----------------
        const float* qi_sh = qsm + qb * 256;       // current tile's q codes
        const float* qj_sh = qi_sh + 128;
        __half2 fih[4], fjh[4];
        #pragma unroll
        for (int mt = 0; mt < 2; mt++) {
            fih[mt * 2 + 0] = __float2half2_rn(qi_sh[wr * 32 + mt * 16 + grp]);
            fih[mt * 2 + 1] = __float2half2_rn(qi_sh[wr * 32 + mt * 16 + grp + 8]);
        }
        #pragma unroll
        for (int nt = 0; nt < 4; nt++) {
            int c0 = wc * 32 + nt * 8 + 2 * qid;
            fjh[nt] = __floats2half2_rn(qj_sh[c0], qj_sh[c0 + 1]);
        }

        __half2 ts2[4], ns2[4], ct2[4], cn2[4];   // tot / neg (rows, cols)
        #pragma unroll
        for (int k = 0; k < 4; k++) {
            ts2[k] = ZERO2; ns2[k] = ZERO2;
            ct2[k] = ZERO2; cn2[k] = ZERO2;
        }

        if (offdiag) {
            #pragma unroll
            for (int mt = 0; mt < 2; mt++)
                #pragma unroll
                for (int nt = 0; nt < 4; nt++)
                    #pragma unroll
                    for (int q = 0; q < 2; q++) {
                        __half2 e = h2ex2(*reinterpret_cast<__half2*>(&acc[mt][nt][q]));
                        __half2 p = __hmul2(fih[mt * 2 + q], fjh[nt]);
                        __half2 m = __hgt2(p, ZERO2);      // tot mask: pos|neg
                        __half2 n = __heq2(p, TWO2);       // neg mask
                        ts2[mt * 2 + q] = __hfma2(e, m, ts2[mt * 2 + q]);
                        ns2[mt * 2 + q] = __hfma2(e, n, ns2[mt * 2 + q]);
                        ct2[nt] = __hfma2(e, m, ct2[nt]);
                        cn2[nt] = __hfma2(e, n, cn2[nt]);
                    }
        } else {
            // Diagonal tile: kill i==j in the tot mask BEFORE accumulation
            // (self term 2^14.4 would swamp fp16 partials). No col sums.
            #pragma unroll
            for (int mt = 0; mt < 2; mt++)
                #pragma unroll
                for (int nt = 0; nt < 4; nt++)
                    #pragma unroll
                    for (int q = 0; q < 2; q++) {
                        int row = wr * 32 + mt * 16 + grp + q * 8;
                        int c0  = wc * 32 + nt * 8 + 2 * qid;
                        __half2 e = h2ex2(*reinterpret_cast<__half2*>(&acc[mt][nt][q]));
                        __half2 p = __hmul2(fih[mt * 2 + q], fjh[nt]);
                        __half2 dk = __floats2half2_rn(row == c0 ? 0.f : 1.f,
                                                       row == c0 + 1 ? 0.f : 1.f);
                        __half2 m = __hmul2(__hgt2(p, ZERO2), dk);
                        __half2 n = __heq2(p, TWO2);
                        ts2[mt * 2 + q] = __hfma2(e, m, ts2[mt * 2 + q]);
                        ns2[mt * 2 + q] = __hfma2(e, n, ns2[mt * 2 + q]);
                    }
        }

        // Row reduce: packed half2 shfl over qid (xor 1,2); unpack at the end.
        #pragma unroll
        for (int r = 0; r < 4; r++) {
            #pragma unroll
            for (int o = 1; o <= 2; o <<= 1) {
                uint32_t ut = __shfl_xor_sync(0xffffffffu, *reinterpret_cast<uint32_t*>(&ts2[r]), o);
                uint32_t un = __shfl_xor_sync(0xffffffffu, *reinterpret_cast<uint32_t*>(&ns2[r]), o);
                ts2[r] = __hadd2(ts2[r], *reinterpret_cast<__half2*>(&ut));
                ns2[r] = __hadd2(ns2[r], *reinterpret_cast<__half2*>(&un));
            }
        }
        if (qid == 0) {
            #pragma unroll
            for (int r = 0; r < 4; r++) {
                int gi = i0 + wr * 32 + (r >> 1) * 16 + grp + (r & 1) * 8;
                float2 tv = __half22float2(ts2[r]);
                float2 nv = __half22float2(ns2[r]);
                float neg = nv.x + nv.y;
                atomicAdd(&g_pos[gi], tv.x + tv.y - neg);
                atomicAdd(&g_neg[gi], neg);
            }
        }

        // Col reduce (off-diag only): packed half2 shfl over grp (xor 4,8,16).
        if (offdiag) {
            #pragma unroll
            for (int c = 0; c < 4; c++) {
                #pragma unroll
                for (int o = 4; o <= 16; o <<= 1) {
                    uint32_t ut = __shfl_xor_sync(0xffffffffu, *reinterpret_cast<uint32_t*>(&ct2[c]), o);
                    uint32_t un = __shfl_xor_sync(0xffffffffu, *reinterpret_cast<uint32_t*>(&cn2[c]), o);
                    ct2[c] = __hadd2(ct2[c], *reinterpret_cast<__half2*>(&ut));
                    cn2[c] = __hadd2(cn2[c], *reinterpret_cast<__half2*>(&un));
                }
            }
            if (grp == 0) {
                #pragma unroll
                for (int c = 0; c < 4; c++) {
                    int gj = j0 + wc * 32 + c * 8 + 2 * qid;
                    float2 tv = __half22float2(ct2[c]);
                    float2 nv = __half22float2(cn2[c]);
                    atomicAdd(&g_pos[gj],     tv.x - nv.x);
                    atomicAdd(&g_pos[gj + 1], tv.y - nv.y);
                    atomicAdd(&g_neg[gj],     nv.x);
                    atomicAdd(&g_neg[gj + 1], nv.y);
                }
            }
        }

        qb ^= 1;
        bb ^= 1;
    }
}

// ---------------------------------------------------------------------------
// Kernel 3: final loss reduction over rows (256 threads, shfl reduce).
// ---------------------------------------------------------------------------
__global__ void loss_kernel(float* __restrict__ out, int B) {
    __shared__ float s1[8], s2[8];
    int tid  = threadIdx.x;
    int lane = tid & 31;
    int wid  = tid >> 5;
    float tot = 0.f, cnt = 0.f;
    for (int i = tid; i < B; i += 256) {
        float p = g_pos[i], n = g_neg[i];
        if (p > 0.f && n > 0.f) {
            tot += -__logf(p / (p + n + 1e-8f));
            cnt += 1.f;
        }
    }
    #pragma unroll
    for (int o = 16; o; o >>= 1) {
        tot += __shfl_xor_sync(0xffffffffu, tot, o);
        cnt += __shfl_xor_sync(0xffffffffu, cnt, o);
    }
    if (lane == 0) { s1[wid] = tot; s2[wid] = cnt; }
    __syncthreads();
    if (wid == 0 && lane < 8) {
        tot = s1[lane]; cnt = s2[lane];
        #pragma unroll
        for (int o = 4; o; o >>= 1) {
            tot += __shfl_xor_sync(0xffu, tot, o);
            cnt += __shfl_xor_sync(0xffu, cnt, o);
        }
        if (lane == 0) out[0] = (cnt > 0.f) ? (tot / cnt) : 0.f;
    }
}

extern "C" void kernel_launch(void* const* d_in, const int* in_sizes, int n_in,
                              void* d_out, int out_size) {
    const float* emb    = (const float*)d_in[0];
    const int*   labels = (const int*)  d_in[1];
    const float* conf   = (const float*)d_in[2];
    int B = in_sizes[1];   // 8192
    (void)n_in; (void)out_size;

    cudaFuncSetAttribute(sim_kernel, cudaFuncAttributeMaxDynamicSharedMemorySize, SMEM_BYTES);

    prep_kernel<<<B / 32, 256>>>(emb, labels, conf);
    sim_kernel<<<GRID_, 512, SMEM_BYTES>>>();
    loss_kernel<<<1, 256>>>((float*)d_out, B);
}

// round 17
// speedup vs baseline: 1.1850x; 1.1769x over previous
#include <cuda_runtime.h>
#include <cuda_fp16.h>
#include <math.h>
#include <stdint.h>

#define B_ 8192
#define D_ 128
#define NT_ 64                            // number of 128-row tiles
#define NPAIRS ((NT_ * (NT_ + 1)) / 2)    // 2080 upper-triangular tile pairs
#define GRID_ 296                         // 2 persistent CTAs per SM

// Smem: A single-buffered (in-place prefetch, lands under epilogue),
// B double-buffered (prefetch issued BEFORE the mainloop -> whole mainloop
// to land). Rows padded to 272B (stride ≡ 16 mod 128 => ldmatrix conflict-free).
#define ROWB 272
#define TILE_BYTES (128 * ROWB)           // 34816
#define OFF_A  0
#define OFF_B0 TILE_BYTES
#define OFF_B1 (2 * TILE_BYTES)
#define OFF_Q  (3 * TILE_BYTES)           // q[2][256] floats
#define SMEM_BYTES (OFF_Q + 2 * 256 * 4)  // 106496 (x2 CTAs = 212992 <= 227KB)

__device__ __align__(16) __half g_eH[B_ * D_];  // scaled by sqrt(log2e/T), fp16
__device__ float g_q[B_];    // class code: sign(conf) * (label==1 ? 1 : 2)
__device__ float g_pos[B_];
__device__ float g_neg[B_];

// ---------------------------------------------------------------------------
__device__ __forceinline__ uint32_t smem_u32(const void* p) {
    uint32_t a;
    asm("{ .reg .u64 t; cvta.to.shared.u64 t, %1; cvt.u32.u64 %0, t; }" : "=r"(a) : "l"(p));
    return a;
}
__device__ __forceinline__ __half2 h2ex2(__half2 x) {
    __half2 y;
    asm("ex2.approx.f16x2 %0, %1;"
        : "=r"(*reinterpret_cast<uint32_t*>(&y))
        : "r"(*reinterpret_cast<uint32_t*>(&x)));
    return y;
}
__device__ __forceinline__ void cpasync16(uint32_t saddr, const void* g) {
    asm volatile("cp.async.cg.shared.global [%0], [%1], 16;" :: "r"(saddr), "l"(g));
}
#define CP_COMMIT() asm volatile("cp.async.commit_group;" ::: "memory")
#define CP_WAIT0()  asm volatile("cp.async.wait_group 0;" ::: "memory")

__device__ __forceinline__ void ldm_x4(uint32_t* r, uint32_t addr) {
    asm volatile("ldmatrix.sync.aligned.m8n8.x4.shared.b16 {%0,%1,%2,%3}, [%4];"
                 : "=r"(r[0]), "=r"(r[1]), "=r"(r[2]), "=r"(r[3]) : "r"(addr));
}
__device__ __forceinline__ void mma_f16acc(uint32_t* d, const uint32_t* a, const uint32_t* b) {
    asm volatile(
        "mma.sync.aligned.m16n8k16.row.col.f16.f16.f16.f16 "
        "{%0,%1}, {%2,%3,%4,%5}, {%6,%7}, {%0,%1};"
        : "+r"(d[0]), "+r"(d[1])
        : "r"(a[0]), "r"(a[1]), "r"(a[2]), "r"(a[3]), "r"(b[0]), "r"(b[1]));
}

// Triangular decode: idx -> (ti, tj), ti <= tj. Float sqrt + exact fixups.
#define FTRI(i) ((i) * (2 * NT_ - (i) + 1) / 2)
__device__ __forceinline__ void tri_decode(int idx, int& ti, int& tj) {
    float f = 2.f * NT_ + 1.f;
    int t = (int)((f - sqrtf(fmaxf(f * f - 8.f * (float)idx, 0.f))) * 0.5f);
    if (t < 0) t = 0;
    if (t > NT_ - 1) t = NT_ - 1;
    while (t > 0 && FTRI(t) > idx) t--;
    while (FTRI(t + 1) <= idx) t++;
    ti = t;
    tj = t + (idx - FTRI(t));
}

// ---------------------------------------------------------------------------
// Kernel 1: normalize rows, fold in sqrt(log2e/T), fp16-round, zero sums.
// 4 warps/block, one warp per row; grid 2048 for fast SM coverage/ramp.
// ---------------------------------------------------------------------------
__global__ void prep_kernel(const float* __restrict__ emb,
                            const int*   __restrict__ labels,
                            const float* __restrict__ conf) {
    int row  = blockIdx.x * 4 + (threadIdx.x >> 5);
    int lane = threadIdx.x & 31;
    float4 v = ((const float4*)(emb + (size_t)row * D_))[lane];
    float ss = v.x*v.x + v.y*v.y + v.z*v.z + v.w*v.w;
    #pragma unroll
    for (int o = 16; o; o >>= 1) ss += __shfl_xor_sync(0xffffffffu, ss, o);
    const float SCALE = 3.7982826f;   // sqrt(log2(e) / 0.1)
    float s = SCALE / fmaxf(sqrtf(ss), 1e-12f);
    __half2 h0 = __floats2half2_rn(v.x * s, v.y * s);
    __half2 h1 = __floats2half2_rn(v.z * s, v.w * s);
    uint2 pk = { *(uint32_t*)&h0, *(uint32_t*)&h1 };
    ((uint2*)(g_eH + (size_t)row * D_))[lane] = pk;
    if (lane == 0) {
        float c = conf[row];
        float sg = (c > 0.f) ? 1.f : ((c < 0.f) ? -1.f : 0.f);
        g_q[row] = sg * ((labels[row] == 1) ? 1.f : 2.f);
        g_pos[row] = 0.f;
        g_neg[row] = 0.f;
    }
}

// ---------------------------------------------------------------------------
// Kernel 2: persistent fp16 mma.sync tiles (2 CTAs/SM). B double-buffered
// (prefetched before the mainloop), A prefetched in place under the epilogue,
// q codes double-buffered. Epilogue: tot/neg half2 accumulation.
// 512 threads = 16 warps (4x4); each warp owns a 32x32 micro-tile.
// ---------------------------------------------------------------------------
__global__ void __launch_bounds__(512, 2) sim_kernel() {
    extern __shared__ char smem[];
    const uint32_t sb = smem_u32(smem);

    const int tid  = threadIdx.x;
    const int wid  = tid >> 5;
    const int lane = tid & 31;
    const int grp  = lane >> 2;     // 0..7
    const int qid  = lane & 3;      // 0..3
    const int wr   = wid >> 2;      // warp row
    const int wc   = wid & 3;       // warp col

    float* qsm = (float*)(smem + OFF_Q);   // [2][256]

    // ldmatrix lane-address components (constant across tiles).
    const uint32_t aAddr0 = sb + OFF_A + (uint32_t)((wr * 32 + (lane & 15)) * ROWB)
                          + (uint32_t)((lane >> 4) * 16);
    const uint32_t bRel   = (uint32_t)((wc * 32 + ((lane >> 4) & 1) * 8 + (lane & 7)) * ROWB)
                          + (uint32_t)(((lane >> 3) & 1) * 16);

    const __half2 ZERO2 = __float2half2_rn(0.f);
    const __half2 TWO2  = __float2half2_rn(2.f);

    // B fill into buffer bbuf.
    auto fill_B = [&](int tj, int bbuf) {
        const char* srcB = (const char*)(g_eH + (size_t)(tj * 128) * D_);
        uint32_t offB = bbuf ? OFF_B1 : OFF_B0;
        #pragma unroll
        for (int it = 0; it < 4; it++) {
            int tt = tid + it * 512;
            int row = tt >> 4, kg = tt & 15;
            uint32_t doff = (uint32_t)(row * ROWB + kg * 16);
            size_t soff = (size_t)row * 256 + (size_t)kg * 16;
            cpasync16(sb + offB + doff, srcB + soff);
        }
        CP_COMMIT();
    };
    // A fill (in place) + q codes for tile (ti, tj) into q buffer qbuf.
    auto fill_A_q = [&](int ti, int tj, int qbuf) {
        const char* srcA = (const char*)(g_eH + (size_t)(ti * 128) * D_);
        #pragma unroll
        for (int it = 0; it < 4; it++) {
            int tt = tid + it * 512;
            int row = tt >> 4, kg = tt & 15;
            uint32_t doff = (uint32_t)(row * ROWB + kg * 16);
            size_t soff = (size_t)row * 256 + (size_t)kg * 16;
            cpasync16(sb + OFF_A + doff, srcA + soff);
        }
        CP_COMMIT();
        if (tid < 128)       qsm[qbuf * 256 + tid] = g_q[ti * 128 + tid];
        else if (tid < 256)  qsm[qbuf * 256 + tid] = g_q[tj * 128 + (tid - 128)];
    };

    // Prologue: fill tile 0 (A + B into buf 0, q into buf 0).
    {
        int ti0, tj0;
        tri_decode(blockIdx.x, ti0, tj0);
        fill_B(tj0, 0);
        fill_A_q(ti0, tj0, 0);
    }

    int qb = 0, bb = 0;
    for (int t = blockIdx.x; t < NPAIRS; t += GRID_) {
        int ti, tj;
        tri_decode(t, ti, tj);
        const int i0 = ti * 128;
        const int j0 = tj * 128;
        const bool offdiag = (ti != tj);

        CP_WAIT0();
        __syncthreads();   // tile t (A + B[bb]) + q codes visible

        // Prefetch NEXT tile's B into the other buffer: gets the whole
        // mainloop + epilogue to land.
        int tn = t + GRID_;
        if (tn < NPAIRS) {
            int tin, tjn;
            tri_decode(tn, tin, tjn);
            fill_B(tjn, bb ^ 1);
        }

        const uint32_t bAddr0 = sb + (bb ? OFF_B1 : OFF_B0) + bRel;

        uint32_t acc[2][4][2] = {};   // [mt][nt][q] half2 accumulators

        #pragma unroll
        for (int ks = 0; ks < 8; ks++) {
            const uint32_t ko = (uint32_t)(ks * 32);   // 16 halves = 32B per kstep
            uint32_t af[2][4], bf[2][4];
            ldm_x4(af[0], aAddr0 + ko);
            ldm_x4(af[1], aAddr0 + (uint32_t)(16 * ROWB) + ko);
            ldm_x4(bf[0], bAddr0 + ko);
            ldm_x4(bf[1], bAddr0 + (uint32_t)(16 * ROWB) + ko);
            #pragma unroll
            for (int mt = 0; mt < 2; mt++)
                #pragma unroll
                for (int nt = 0; nt < 4; nt++)
                    mma_f16acc(acc[mt][nt], af[mt], &bf[nt >> 1][(nt & 1) * 2]);
        }

        __syncthreads();   // all warps done reading A tile + qsm[qb^1] free

        // Prefetch next tile's A in place + q codes; lands under the epilogue.
        if (tn < NPAIRS) {
            int tin, tjn;
            tri_decode(tn, tin, tjn);
            fill_A_q(tin, tjn, qb ^ 1);
        }

        // ---------------- Epilogue (half2): tot/neg accumulation ----------------
        const float* qi_sh = qsm + qb * 256;       // current tile's q codes
        const float* qj_sh = qi_sh + 128;
        __half2 fih[4], fjh[4];
        #pragma unroll
        for (int mt = 0; mt < 2; mt++) {
            fih[mt * 2 + 0] = __float2half2_rn(qi_sh[wr * 32 + mt * 16 + grp]);
            fih[mt * 2 + 1] = __float2half2_rn(qi_sh[wr * 32 + mt * 16 + grp + 8]);
        }
        #pragma unroll
        for (int nt = 0; nt < 4; nt++) {
            int c0 = wc * 32 + nt * 8 + 2 * qid;
            fjh[nt] = __floats2half2_rn(qj_sh[c0], qj_sh[c0 + 1]);
        }

        __half2 ts2[4], ns2[4], ct2[4], cn2[4];   // tot / neg (rows, cols)
        #pragma unroll
        for (int k = 0; k < 4; k++) {
            ts2[k] = ZERO2; ns2[k] = ZERO2;
            ct2[k] = ZERO2; cn2[k] = ZERO2;
        }

        if (offdiag) {
            #pragma unroll
            for (int mt = 0; mt < 2; mt++)
                #pragma unroll
                for (int nt = 0; nt < 4; nt++)
                    #pragma unroll
                    for (int q = 0; q < 2; q++) {
                        __half2 e = h2ex2(*reinterpret_cast<__half2*>(&acc[mt][nt][q]));
                        __half2 p = __hmul2(fih[mt * 2 + q], fjh[nt]);
                        __half2 m = __hgt2(p, ZERO2);      // tot mask: pos|neg
                        __half2 n = __heq2(p, TWO2);       // neg mask
                        ts2[mt * 2 + q] = __hfma2(e, m, ts2[mt * 2 + q]);
                        ns2[mt * 2 + q] = __hfma2(e, n, ns2[mt * 2 + q]);
                        ct2[nt] = __hfma2(e, m, ct2[nt]);
                        cn2[nt] = __hfma2(e, n, cn2[nt]);
                    }
        } else {
            // Diagonal tile: kill i==j in the tot mask BEFORE accumulation
            // (self term 2^14.4 would swamp fp16 partials). No col sums.
            #pragma unroll
            for (int mt = 0; mt < 2; mt++)
                #pragma unroll
                for (int nt = 0; nt < 4; nt++)
                    #pragma unroll
                    for (int q = 0; q < 2; q++) {
                        int row = wr * 32 + mt * 16 + grp + q * 8;
                        int c0  = wc * 32 + nt * 8 + 2 * qid;
                        __half2 e = h2ex2(*reinterpret_cast<__half2*>(&acc[mt][nt][q]));
                        __half2 p = __hmul2(fih[mt * 2 + q], fjh[nt]);
                        __half2 dk = __floats2half2_rn(row == c0 ? 0.f : 1.f,
                                                       row == c0 + 1 ? 0.f : 1.f);
                        __half2 m = __hmul2(__hgt2(p, ZERO2), dk);
                        __half2 n = __heq2(p, TWO2);
                        ts2[mt * 2 + q] = __hfma2(e, m, ts2[mt * 2 + q]);
                        ns2[mt * 2 + q] = __hfma2(e, n, ns2[mt * 2 + q]);
                    }
        }

        // Row reduce: packed half2 shfl over qid (xor 1,2); unpack at the end.
        #pragma unroll
        for (int r = 0; r < 4; r++) {
            #pragma unroll
            for (int o = 1; o <= 2; o <<= 1) {
                uint32_t ut = __shfl_xor_sync(0xffffffffu, *reinterpret_cast<uint32_t*>(&ts2[r]), o);
                uint32_t un = __shfl_xor_sync(0xffffffffu, *reinterpret_cast<uint32_t*>(&ns2[r]), o);
                ts2[r] = __hadd2(ts2[r], *reinterpret_cast<__half2*>(&ut));
                ns2[r] = __hadd2(ns2[r], *reinterpret_cast<__half2*>(&un));
            }
        }
        if (qid == 0) {
            #pragma unroll
            for (int r = 0; r < 4; r++) {
                int gi = i0 + wr * 32 + (r >> 1) * 16 + grp + (r & 1) * 8;
                float2 tv = __half22float2(ts2[r]);
                float2 nv = __half22float2(ns2[r]);
                float neg = nv.x + nv.y;
                atomicAdd(&g_pos[gi], tv.x + tv.y - neg);
                atomicAdd(&g_neg[gi], neg);
            }
        }

        // Col reduce (off-diag only): packed half2 shfl over grp (xor 4,8,16).
        if (offdiag) {
            #pragma unroll
            for (int c = 0; c < 4; c++) {
                #pragma unroll
                for (int o = 4; o <= 16; o <<= 1) {
                    uint32_t ut = __shfl_xor_sync(0xffffffffu, *reinterpret_cast<uint32_t*>(&ct2[c]), o);
                    uint32_t un = __shfl_xor_sync(0xffffffffu, *reinterpret_cast<uint32_t*>(&cn2[c]), o);
                    ct2[c] = __hadd2(ct2[c], *reinterpret_cast<__half2*>(&ut));
                    cn2[c] = __hadd2(cn2[c], *reinterpret_cast<__half2*>(&un));
                }
            }
            if (grp == 0) {
                #pragma unroll
                for (int c = 0; c < 4; c++) {
                    int gj = j0 + wc * 32 + c * 8 + 2 * qid;
                    float2 tv = __half22float2(ct2[c]);
                    float2 nv = __half22float2(cn2[c]);
                    atomicAdd(&g_pos[gj],     tv.x - nv.x);
                    atomicAdd(&g_pos[gj + 1], tv.y - nv.y);
                    atomicAdd(&g_neg[gj],     nv.x);
                    atomicAdd(&g_neg[gj + 1], nv.y);
                }
            }
        }

        qb ^= 1;
        bb ^= 1;
    }
}

// ---------------------------------------------------------------------------
// Kernel 3: final loss reduction over rows (1024 threads, shfl reduce).
// ---------------------------------------------------------------------------
__global__ void loss_kernel(float* __restrict__ out, int B) {
    __shared__ float s1[32], s2[32];
    int tid  = threadIdx.x;
    int lane = tid & 31;
    int wid  = tid >> 5;
    float tot = 0.f, cnt = 0.f;
    for (int i = tid; i < B; i += 1024) {
        float p = g_pos[i], n = g_neg[i];
        if (p > 0.f && n > 0.f) {
            tot += -__logf(p / (p + n + 1e-8f));
            cnt += 1.f;
        }
    }
    #pragma unroll
    for (int o = 16; o; o >>= 1) {
        tot += __shfl_xor_sync(0xffffffffu, tot, o);
        cnt += __shfl_xor_sync(0xffffffffu, cnt, o);
    }
    if (lane == 0) { s1[wid] = tot; s2[wid] = cnt; }
    __syncthreads();
    if (wid == 0) {
        tot = s1[lane]; cnt = s2[lane];
        #pragma unroll
        for (int o = 16; o; o >>= 1) {
            tot += __shfl_xor_sync(0xffffffffu, tot, o);
            cnt += __shfl_xor_sync(0xffffffffu, cnt, o);
        }
        if (lane == 0) out[0] = (cnt > 0.f) ? (tot / cnt) : 0.f;
    }
}

extern "C" void kernel_launch(void* const* d_in, const int* in_sizes, int n_in,
                              void* d_out, int out_size) {
    const float* emb    = (const float*)d_in[0];
    const int*   labels = (const int*)  d_in[1];
    const float* conf   = (const float*)d_in[2];
    int B = in_sizes[1];   // 8192
    (void)n_in; (void)out_size;

    cudaFuncSetAttribute(sim_kernel, cudaFuncAttributeMaxDynamicSharedMemorySize, SMEM_BYTES);

    prep_kernel<<<B / 4, 128>>>(emb, labels, conf);
    sim_kernel<<<GRID_, 512, SMEM_BYTES>>>();
    loss_kernel<<<1, 1024>>>((float*)d_out, B);
}